// round 14
// baseline (speedup 1.0000x reference)
#include <cuda_runtime.h>
#include <math.h>
#include <stdint.h>

// ---------------------------------------------------------------------------
// Multi-scale region distillation loss — single kernel, WARP-PRIVATE cp.async
// pipelines.
//
// R14: R13 (block-wide pipeline) stuck at DRAM 49% with issue 30% / occ 55% —
// nothing saturated. Diagnosis: block-wide wait+syncthreads each iteration
// makes 8 warps wait for the slowest of 512 cp16s (convoy effect; L2/DRAM
// latency variance). Fix: each warp owns 32 pixels and a private 5-stage
// ring (1KB/stage = 4ch x 32px x {f,fo}); waits only on its own cp groups
// (wait_group + __syncwarp). No __syncthreads in the hot loop at all.
//
// Per SM: 5 blocks x 8 warps x ~4KB in flight = 160KB. 680 blocks = 1 wave.
// ---------------------------------------------------------------------------

#define NUM_SCALES 4
#define MAXC 32
#define LAB_DIM 512
#define THREADS 256
#define NWARP 8
#define PXW 32                  // pixels per warp
#define PXB (NWARP * PXW)       // 256 pixels per block
#define STAGES 5
#define CPS 4                   // channels per stage
#define STAGE_FLOATS (CPS * PXW * 2)      // 256 floats = 1KB per warp-stage

__device__ double       g_seg[NUM_SCALES * MAXC];   // zero-init at load
__device__ float        g_cnt[NUM_SCALES * MAXC];   // zero-init at load
__device__ unsigned int g_blocks_done = 0;          // zero-init at load

struct ScaleDesc {
    const float* f;
    const float* fo;
    int C;           // channels
    int W;           // spatial width (=H)
    int HW;          // H*W
    int block_base;  // first block of this scale
    int sub;         // LAB_DIM / H
};
struct AllDesc { ScaleDesc s[NUM_SCALES]; };

__device__ __forceinline__ void cp16(uint32_t dst, const void* src) {
    asm volatile("cp.async.cg.shared.global [%0], [%1], 16;"
                 :: "r"(dst), "l"(src) : "memory");
}
__device__ __forceinline__ void cp_commit() {
    asm volatile("cp.async.commit_group;" ::: "memory");
}
__device__ __forceinline__ void cp_wait3() {
    asm volatile("cp.async.wait_group 3;" ::: "memory");
}

__global__ void __launch_bounds__(THREADS, 5)
msrd_kernel(AllDesc d, const int* __restrict__ lab,
            const int* __restrict__ ncls_p, const int* __restrict__ nold_p,
            float* __restrict__ out)
{
    // [warp][stage][f:128 | fo:128] floats = 8 * 5 * 1KB = 40KB
    __shared__ float s_tile[NWARP][STAGES][STAGE_FLOATS];
    __shared__ float s_seg[MAXC];
    __shared__ float s_cnt[MAXC];
    __shared__ int   s_is_last;

    const int t    = (int)threadIdx.x;
    const int warp = t >> 5;
    const int lane = t & 31;
    if (t < MAXC) { s_seg[t] = 0.f; s_cnt[t] = 0.f; }
    __syncthreads();   // s_seg/s_cnt ready before any warp's epilogue atomics

    int sidx;
    if      ((int)blockIdx.x < d.s[1].block_base) sidx = 0;
    else if ((int)blockIdx.x < d.s[2].block_base) sidx = 1;
    else if ((int)blockIdx.x < d.s[3].block_base) sidx = 2;
    else                                          sidx = 3;
    const ScaleDesc sd = d.s[sidx];

    const int chunk = (int)blockIdx.x - sd.block_base;
    const int px0   = chunk * PXB + warp * PXW;   // this warp's first pixel
    const int b     = px0 / sd.HW;                // PXB divides HW
    const int p0    = px0 - b * sd.HW;
    const int HW    = sd.HW;
    const int C     = sd.C;
    const int ngrp  = C / CPS;                    // 64 channel groups

    // cp.async source: lane covers channel (lane>>3) of the stage, 16B part
    // (lane&7) of this warp's 128B pixel row.
    const float* __restrict__ fA = sd.f  + (size_t)b * C * HW + p0;
    const float* __restrict__ fO = sd.fo + (size_t)b * C * HW + p0;
    const float* srcA0 = fA + (size_t)(lane >> 3) * HW + (lane & 7) * 4;
    const float* srcO0 = fO + (size_t)(lane >> 3) * HW + (lane & 7) * 4;
    const size_t grp_stride = (size_t)CPS * HW;

    const uint32_t warp_base =
        (uint32_t)__cvta_generic_to_shared(&s_tile[warp][0][0]);
    const uint32_t dstA = (uint32_t)(((lane >> 3) * 32 + (lane & 7) * 4) * 4);
    const uint32_t dstO = dstA + (uint32_t)(CPS * PXW * 4);   // +512B

    // ---------------- prologue: groups 0..3 ----------------
    #pragma unroll
    for (int g = 0; g < STAGES - 1; ++g) {
        const uint32_t sb = warp_base + (uint32_t)g * (STAGE_FLOATS * 4);
        cp16(sb + dstA, srcA0 + (size_t)g * grp_stride);
        cp16(sb + dstO, srcO0 + (size_t)g * grp_stride);
        cp_commit();
    }

    // ---------------- hot loop: NO block barriers ----------------
    float dot = 0.f, na = 0.f, nb = 0.f;
    int sl = 0;
    #pragma unroll 1
    for (int g = 0; g < ngrp; ++g) {
        cp_wait3();          // this warp's group g landed
        __syncwarp();

        const float* __restrict__ fa  = &s_tile[warp][sl][0];
        const float* __restrict__ fo2 = &s_tile[warp][sl][CPS * PXW];
        float a0 = fa [0 * PXW + lane], o0 = fo2[0 * PXW + lane];
        float a1 = fa [1 * PXW + lane], o1 = fo2[1 * PXW + lane];
        float a2 = fa [2 * PXW + lane], o2 = fo2[2 * PXW + lane];
        float a3 = fa [3 * PXW + lane], o3 = fo2[3 * PXW + lane];
        dot = fmaf(a0, o0, dot); na = fmaf(a0, a0, na); nb = fmaf(o0, o0, nb);
        dot = fmaf(a1, o1, dot); na = fmaf(a1, a1, na); nb = fmaf(o1, o1, nb);
        dot = fmaf(a2, o2, dot); na = fmaf(a2, a2, na); nb = fmaf(o2, o2, nb);
        dot = fmaf(a3, o3, dot); na = fmaf(a3, a3, na); nb = fmaf(o3, o3, nb);

        __syncwarp();        // all lanes done reading slot before refill
        const int gn = g + STAGES - 1;
        if (gn < ngrp) {
            const uint32_t sb = warp_base
                + (uint32_t)((gn >= STAGES) ? gn - STAGES : gn) * 0  // dummy
                + (uint32_t)(( (gn % STAGES) ) * (STAGE_FLOATS * 4));
            cp16(sb + dstA, srcA0 + (size_t)gn * grp_stride);
            cp16(sb + dstO, srcO0 + (size_t)gn * grp_stride);
        }
        cp_commit();

        if (++sl == STAGES) sl = 0;
    }

    // ---------------- per-pixel epilogue ----------------
    {
        const float nf  = fmaxf(sqrtf(na), 1e-8f);
        const float nfo = fmaxf(sqrtf(nb), 1e-8f);
        const float sim = dot / (nf * nfo);

        const int p = p0 + lane;
        const int h = p / sd.W;
        const int w = p - h * sd.W;
        const int l = lab[(size_t)b * LAB_DIM * LAB_DIM
                          + (size_t)(h * sd.sub) * LAB_DIM + (size_t)w * sd.sub];
        if (l >= 0 && l < MAXC) {
            atomicAdd(&s_seg[l], sim);
            atomicAdd(&s_cnt[l], 1.0f);
        }
    }

    __syncthreads();
    if (t < MAXC) {
        const float cs = s_cnt[t];
        if (cs != 0.0f) {
            atomicAdd(&g_seg[sidx * MAXC + t], (double)s_seg[t]);
            atomicAdd(&g_cnt[sidx * MAXC + t], cs);
        }
    }

    // ---------------- last-block finalize ----------------
    __syncthreads();
    if (t == 0) {
        __threadfence();
        const unsigned int done = atomicAdd(&g_blocks_done, 1u);
        s_is_last = (done == gridDim.x - 1) ? 1 : 0;
    }
    __syncthreads();
    if (!s_is_last) return;

    __threadfence();
    if (t == 0) {
        const int nc = ncls_p ? *ncls_p : 21;
        const int no = nold_p ? *nold_p : 15;
        const double wts[NUM_SCALES] = {1.0, 2.0, 3.0, 4.0};
        double loss = 0.0;
        for (int s = 0; s < NUM_SCALES; ++s) {
            for (int cls = 0; cls < nc && cls < MAXC; ++cls) {
                const float cnt = g_cnt[s * MAXC + cls];
                if (cnt > 0.0f) {
                    const double mean = g_seg[s * MAXC + cls] / (double)cnt;
                    double factor;
                    if (cls == 0)        factor = (double)no / (double)nc;
                    else if (cls <= no)  factor = 1.0;
                    else                 factor = 0.0;
                    loss += wts[s] * factor * (1.0 - mean);
                }
            }
        }
        *out = (float)loss;
    }

    __syncthreads();   // loss read complete before resets
    if (t == 0) g_blocks_done = 0;
    if (t < NUM_SCALES * MAXC / 2) {
        const int r = t * 2;
        g_seg[r] = 0.0;  g_seg[r + 1] = 0.0;
        g_cnt[r] = 0.0f; g_cnt[r + 1] = 0.0f;
    }
}

extern "C" void kernel_launch(void* const* d_in, const int* in_sizes, int n_in,
                              void* d_out, int out_size)
{
    const int* lab = (const int*)d_in[0];
    const int B = in_sizes[0] / (LAB_DIM * LAB_DIM);

    // ---- identify feature buffers by size (order-agnostic) ----
    const float* fbuf[NUM_SCALES]  = {nullptr, nullptr, nullptr, nullptr};
    const float* fobuf[NUM_SCALES] = {nullptr, nullptr, nullptr, nullptr};
    long         szs[NUM_SCALES]   = {0, 0, 0, 0};
    int ns = 0;
    const int* scalar_ptrs[2] = {nullptr, nullptr};
    int nscalar = 0;

    for (int i = 1; i < n_in; ++i) {
        const long sz = in_sizes[i];
        if (sz <= 1) {
            if (nscalar < 2) scalar_ptrs[nscalar++] = (const int*)d_in[i];
            continue;
        }
        int j = 0;
        while (j < ns && szs[j] != sz) ++j;
        if (j == ns && ns < NUM_SCALES) {
            szs[ns] = sz; fbuf[ns] = (const float*)d_in[i]; ++ns;
        } else if (j < ns) {
            fobuf[j] = (const float*)d_in[i];
        }
    }
    for (int i = 0; i < ns; ++i)
        for (int j = i + 1; j < ns; ++j)
            if (szs[j] > szs[i]) {
                long ts = szs[i]; szs[i] = szs[j]; szs[j] = ts;
                const float* tf = fbuf[i]; fbuf[i] = fbuf[j]; fbuf[j] = tf;
                const float* to = fobuf[i]; fobuf[i] = fobuf[j]; fobuf[j] = to;
            }

    // ---- per-scale descriptors (uniform 256-px chunks) ----
    AllDesc ad;
    int block_base = 0;
    for (int s = 0; s < NUM_SCALES; ++s) {
        const int HW_dim = 128 >> s;             // 128,64,32,16
        const int HW     = HW_dim * HW_dim;
        const int C      = (int)(szs[s] / ((long)B * HW));
        const int pixels = B * HW;
        const int nblk   = pixels / PXB;

        ad.s[s].f          = fbuf[s];
        ad.s[s].fo         = fobuf[s];
        ad.s[s].C          = C;
        ad.s[s].W          = HW_dim;
        ad.s[s].HW         = HW;
        ad.s[s].block_base = block_base;
        ad.s[s].sub        = LAB_DIM / HW_dim;
        block_base += nblk;
    }

    msrd_kernel<<<block_base, THREADS>>>(ad, lab,
                                         scalar_ptrs[0], scalar_ptrs[1],
                                         (float*)d_out);
}

// round 15
// speedup vs baseline: 1.0305x; 1.0305x over previous
#include <cuda_runtime.h>
#include <math.h>
#include <stdint.h>

// ---------------------------------------------------------------------------
// Multi-scale region distillation loss — single kernel, BULK-ASYNC (TMA-class)
// pipeline.
//
// R15: four SM-issued load engines (LDG scalar/vector, cp.async block/warp)
// all capped at 3.6-3.9TB/s regardless of occupancy/MLP/granularity -> the
// per-SM request path itself binds. cp.async.bulk (UBLKCP) is serviced by
// the bulk/TMA engine (documented to reach the ~6300B/cyc LTS cap), not by
// per-thread LSU requests. Each channel row of a 256-px chunk is 1KB
// contiguous -> one bulk copy per row: 8 instructions per 8KB stage.
//
// Geometry: block = 256px x 256ch (680 uniform blocks). 4-stage ring,
// stage = 4 channels (f 4KB + fo 4KB), mbarrier expect_tx completion.
// ---------------------------------------------------------------------------

#define NUM_SCALES 4
#define MAXC 32
#define LAB_DIM 512
#define THREADS 256
#define PXB 256                 // pixels per block/chunk
#define STAGES 4
#define CPS 4                   // channels per stage
#define STAGE_BYTES (CPS * PXB * 4 * 2)   // 8192

__device__ double       g_seg[NUM_SCALES * MAXC];   // zero-init at load
__device__ float        g_cnt[NUM_SCALES * MAXC];   // zero-init at load
__device__ unsigned int g_blocks_done = 0;          // zero-init at load

struct ScaleDesc {
    const float* f;
    const float* fo;
    int C;           // channels
    int W;           // spatial width (=H)
    int HW;          // H*W
    int block_base;  // first block of this scale
    int sub;         // LAB_DIM / H
};
struct AllDesc { ScaleDesc s[NUM_SCALES]; };

__device__ __forceinline__ uint32_t smem_u32(const void* p) {
    return (uint32_t)__cvta_generic_to_shared(p);
}
__device__ __forceinline__ void bulk_cp(uint32_t dst, const void* src,
                                        uint32_t bytes, uint32_t mbar) {
    asm volatile(
        "cp.async.bulk.shared::cta.global.mbarrier::complete_tx::bytes "
        "[%0], [%1], %2, [%3];"
        :: "r"(dst), "l"(src), "r"(bytes), "r"(mbar) : "memory");
}
__device__ __forceinline__ void mbar_init(uint32_t mbar, uint32_t count) {
    asm volatile("mbarrier.init.shared.b64 [%0], %1;"
                 :: "r"(mbar), "r"(count) : "memory");
}
__device__ __forceinline__ void mbar_expect_tx(uint32_t mbar, uint32_t bytes) {
    asm volatile("mbarrier.arrive.expect_tx.shared.b64 _, [%0], %1;"
                 :: "r"(mbar), "r"(bytes) : "memory");
}
__device__ __forceinline__ void mbar_wait(uint32_t mbar, uint32_t parity) {
    asm volatile(
        "{\n\t"
        ".reg .pred P;\n\t"
        "WAIT_%=: mbarrier.try_wait.parity.acquire.cta.shared::cta.b64 "
        "P, [%0], %1, 0x989680;\n\t"
        "@P bra.uni DONE_%=;\n\t"
        "bra.uni WAIT_%=;\n\t"
        "DONE_%=:\n\t"
        "}"
        :: "r"(mbar), "r"(parity) : "memory");
}

__global__ void __launch_bounds__(THREADS, 5)
msrd_kernel(AllDesc d, const int* __restrict__ lab,
            const int* __restrict__ ncls_p, const int* __restrict__ nold_p,
            float* __restrict__ out)
{
    // [stage][f/fo][ch][px] = 4*2*4*256 floats = 32KB
    __shared__ float s_tile[STAGES][2][CPS][PXB];
    __shared__ __align__(8) unsigned long long s_mbar[STAGES];
    __shared__ float s_seg[MAXC];
    __shared__ float s_cnt[MAXC];
    __shared__ int   s_is_last;

    const int t = (int)threadIdx.x;
    if (t < MAXC) { s_seg[t] = 0.f; s_cnt[t] = 0.f; }
    if (t < STAGES) mbar_init(smem_u32(&s_mbar[t]), 1);
    __syncthreads();

    int sidx;
    if      ((int)blockIdx.x < d.s[1].block_base) sidx = 0;
    else if ((int)blockIdx.x < d.s[2].block_base) sidx = 1;
    else if ((int)blockIdx.x < d.s[3].block_base) sidx = 2;
    else                                          sidx = 3;
    const ScaleDesc sd = d.s[sidx];

    const int chunk = (int)blockIdx.x - sd.block_base;
    const int px0   = chunk * PXB;               // pixel offset within scale
    const int b     = px0 / sd.HW;               // PXB divides HW
    const int p0    = px0 - b * sd.HW;
    const int HW    = sd.HW;
    const int C     = sd.C;
    const int ngrp  = C / CPS;                   // 64 channel groups

    const float* __restrict__ fA = sd.f  + (size_t)b * C * HW + p0;
    const float* __restrict__ fO = sd.fo + (size_t)b * C * HW + p0;

    // producer: issue 8 bulk copies (4 ch x {f,fo}) for channel group gn
    auto issue_group = [&](int gn) {
        const int sl = gn & (STAGES - 1);
        const uint32_t mbar = smem_u32(&s_mbar[sl]);
        mbar_expect_tx(mbar, STAGE_BYTES);
        const size_t c0 = (size_t)gn * CPS;
        #pragma unroll
        for (int c = 0; c < CPS; ++c) {
            bulk_cp(smem_u32(&s_tile[sl][0][c][0]),
                    fA + (c0 + c) * HW, PXB * 4, mbar);
            bulk_cp(smem_u32(&s_tile[sl][1][c][0]),
                    fO + (c0 + c) * HW, PXB * 4, mbar);
        }
    };

    // ---------------- prologue: groups 0..2 ----------------
    if (t == 0) {
        issue_group(0);
        issue_group(1);
        issue_group(2);
    }

    // ---------------- main loop over channel groups ----------------
    float dot = 0.f, na = 0.f, nb = 0.f;
    #pragma unroll 1
    for (int g = 0; g < ngrp; ++g) {
        const int sl = g & (STAGES - 1);
        mbar_wait(smem_u32(&s_mbar[sl]), (g >> 2) & 1);

        #pragma unroll
        for (int c = 0; c < CPS; ++c) {
            const float a = s_tile[sl][0][c][t];
            const float o = s_tile[sl][1][c][t];
            dot = fmaf(a, o, dot);
            na  = fmaf(a, a, na);
            nb  = fmaf(o, o, nb);
        }

        __syncthreads();   // all threads done with slot (g-1)%4 and g%4 reads
        const int gn = g + STAGES - 1;
        if (t == 0 && gn < ngrp) issue_group(gn);
    }

    // ---------------- per-pixel epilogue ----------------
    {
        const float nf  = fmaxf(sqrtf(na), 1e-8f);
        const float nfo = fmaxf(sqrtf(nb), 1e-8f);
        const float sim = dot / (nf * nfo);

        const int p = p0 + t;
        const int h = p / sd.W;
        const int w = p - h * sd.W;
        const int l = lab[(size_t)b * LAB_DIM * LAB_DIM
                          + (size_t)(h * sd.sub) * LAB_DIM + (size_t)w * sd.sub];
        if (l >= 0 && l < MAXC) {
            atomicAdd(&s_seg[l], sim);
            atomicAdd(&s_cnt[l], 1.0f);
        }
    }

    __syncthreads();
    if (t < MAXC) {
        const float cs = s_cnt[t];
        if (cs != 0.0f) {
            atomicAdd(&g_seg[sidx * MAXC + t], (double)s_seg[t]);
            atomicAdd(&g_cnt[sidx * MAXC + t], cs);
        }
    }

    // ---------------- last-block finalize ----------------
    __syncthreads();
    if (t == 0) {
        __threadfence();
        const unsigned int done = atomicAdd(&g_blocks_done, 1u);
        s_is_last = (done == gridDim.x - 1) ? 1 : 0;
    }
    __syncthreads();
    if (!s_is_last) return;

    __threadfence();
    if (t == 0) {
        const int nc = ncls_p ? *ncls_p : 21;
        const int no = nold_p ? *nold_p : 15;
        const double wts[NUM_SCALES] = {1.0, 2.0, 3.0, 4.0};
        double loss = 0.0;
        for (int s = 0; s < NUM_SCALES; ++s) {
            for (int cls = 0; cls < nc && cls < MAXC; ++cls) {
                const float cnt = g_cnt[s * MAXC + cls];
                if (cnt > 0.0f) {
                    const double mean = g_seg[s * MAXC + cls] / (double)cnt;
                    double factor;
                    if (cls == 0)        factor = (double)no / (double)nc;
                    else if (cls <= no)  factor = 1.0;
                    else                 factor = 0.0;
                    loss += wts[s] * factor * (1.0 - mean);
                }
            }
        }
        *out = (float)loss;
    }

    __syncthreads();   // loss read complete before resets
    if (t == 0) g_blocks_done = 0;
    if (t < NUM_SCALES * MAXC / 2) {
        const int r = t * 2;
        g_seg[r] = 0.0;  g_seg[r + 1] = 0.0;
        g_cnt[r] = 0.0f; g_cnt[r + 1] = 0.0f;
    }
}

extern "C" void kernel_launch(void* const* d_in, const int* in_sizes, int n_in,
                              void* d_out, int out_size)
{
    const int* lab = (const int*)d_in[0];
    const int B = in_sizes[0] / (LAB_DIM * LAB_DIM);

    // ---- identify feature buffers by size (order-agnostic) ----
    const float* fbuf[NUM_SCALES]  = {nullptr, nullptr, nullptr, nullptr};
    const float* fobuf[NUM_SCALES] = {nullptr, nullptr, nullptr, nullptr};
    long         szs[NUM_SCALES]   = {0, 0, 0, 0};
    int ns = 0;
    const int* scalar_ptrs[2] = {nullptr, nullptr};
    int nscalar = 0;

    for (int i = 1; i < n_in; ++i) {
        const long sz = in_sizes[i];
        if (sz <= 1) {
            if (nscalar < 2) scalar_ptrs[nscalar++] = (const int*)d_in[i];
            continue;
        }
        int j = 0;
        while (j < ns && szs[j] != sz) ++j;
        if (j == ns && ns < NUM_SCALES) {
            szs[ns] = sz; fbuf[ns] = (const float*)d_in[i]; ++ns;
        } else if (j < ns) {
            fobuf[j] = (const float*)d_in[i];
        }
    }
    for (int i = 0; i < ns; ++i)
        for (int j = i + 1; j < ns; ++j)
            if (szs[j] > szs[i]) {
                long ts = szs[i]; szs[i] = szs[j]; szs[j] = ts;
                const float* tf = fbuf[i]; fbuf[i] = fbuf[j]; fbuf[j] = tf;
                const float* to = fobuf[i]; fobuf[i] = fobuf[j]; fobuf[j] = to;
            }

    // ---- per-scale descriptors (uniform 256-px chunks) ----
    AllDesc ad;
    int block_base = 0;
    for (int s = 0; s < NUM_SCALES; ++s) {
        const int HW_dim = 128 >> s;             // 128,64,32,16
        const int HW     = HW_dim * HW_dim;
        const int C      = (int)(szs[s] / ((long)B * HW));
        const int pixels = B * HW;
        const int nblk   = pixels / PXB;

        ad.s[s].f          = fbuf[s];
        ad.s[s].fo         = fobuf[s];
        ad.s[s].C          = C;
        ad.s[s].W          = HW_dim;
        ad.s[s].HW         = HW;
        ad.s[s].block_base = block_base;
        ad.s[s].sub        = LAB_DIM / HW_dim;
        block_base += nblk;
    }

    msrd_kernel<<<block_base, THREADS>>>(ad, lab,
                                         scalar_ptrs[0], scalar_ptrs[1],
                                         (float*)d_out);
}